// round 15
// baseline (speedup 1.0000x reference)
#include <cuda_runtime.h>
#include <cuda_bf16.h>
#include <math.h>
#include <stdint.h>

#define N_PTS 8192
#define C_DIM 256
#define KNN   16

// ---------------- scratch (device globals; no allocations allowed) ----------
__device__ int   g_idx[N_PTS * KNN];
__device__ float g_delta[N_PTS * KNN * 3];
__device__ float g_theta[N_PTS * C_DIM];
__device__ float g_phi[N_PTS * C_DIM];
__device__ float g_gf[N_PTS * C_DIM];
__device__ float g_y[N_PTS * C_DIM];
__device__ __nv_bfloat16 g_w2t[C_DIM * C_DIM];   // w2 transposed, bf16: [n][k]

// ---------------- grid-KNN scratch (coarse grid: 8^3, cell = 12.5) ----------
#define GRES   8
#define NCELLS (GRES * GRES * GRES)
#define CELLSZ 12.5f
__device__ int    g_cell_cnt[NCELLS];    // zero-init at load; scan re-zeroes
__device__ int    g_cell_off[NCELLS + 1];
__device__ int    g_cell_cur[NCELLS];
__device__ float4 g_sorted[N_PTS];       // (x, y, z, bitcast orig idx)

__device__ __forceinline__ int cell_coord(float x) {
    int c = (int)(x * 0.08f);            // 8 / 100
    return min(GRES - 1, max(0, c));
}

__global__ void cell_count_kernel(const float* __restrict__ coords) {
    int q = blockIdx.x * 256 + threadIdx.x;
    int cx = cell_coord(coords[q * 3 + 0]);
    int cy = cell_coord(coords[q * 3 + 1]);
    int cz = cell_coord(coords[q * 3 + 2]);
    atomicAdd(&g_cell_cnt[(cx * GRES + cy) * GRES + cz], 1);
}

// single block, 512 threads, 1 cell each: exclusive prefix sum over 512.
// Also re-zeroes g_cell_cnt for the next graph replay (self-restoring state).
__global__ void cell_scan_kernel() {
    __shared__ int part[512];
    int t = threadIdx.x;
    int v = g_cell_cnt[t];
    g_cell_cnt[t] = 0;                 // ready for next replay's count pass
    part[t] = v;
    __syncthreads();
    for (int off = 1; off < 512; off <<= 1) {
        int u = (t >= off) ? part[t - off] : 0;
        __syncthreads();
        part[t] += u;
        __syncthreads();
    }
    int excl = part[t] - v;
    g_cell_off[t] = excl;
    g_cell_cur[t] = excl;
    if (t == 511) g_cell_off[NCELLS] = excl + v;
}

__global__ void cell_scatter_kernel(const float* __restrict__ coords) {
    int q = blockIdx.x * 256 + threadIdx.x;
    float x = coords[q * 3 + 0], y = coords[q * 3 + 1], z = coords[q * 3 + 2];
    int cell = (cell_coord(x) * GRES + cell_coord(y)) * GRES + cell_coord(z);
    int pos = atomicAdd(&g_cell_cur[cell], 1);
    g_sorted[pos] = make_float4(x, y, z, __int_as_float(q));
}

// ---------------- grid KNN v5: u64 keys, 8 threads/query --------------------
// key = (ordered(d2) << 32) | idx; integer order == lexicographic (d2, idx)
// == jax.lax.top_k stable order. 8 lanes per query: per-lane serial path
// shortens ~0.7x and resident warps double vs the 4-lane version (the kernel
// is latency-bound: occ 9.5%, issue 27%, alu 15.6% in R14's profile).
#define TPQ  8
#define KQPB 32    // queries per block (256 threads / 8)

__device__ __forceinline__ uint32_t ord_f32(float f) {
    uint32_t u = __float_as_uint(f);
    u ^= (uint32_t)((int)u >> 31) | 0x80000000u;
    return u;
}

#define SCAN_SPAN(S, E)                                                        \
    for (int p = (S) + g; p < (E); p += TPQ) {                                 \
        float4 c = g_sorted[p];                                                \
        float cs2 = c.x * c.x + c.y * c.y + c.z * c.z;                         \
        float dot = qx * c.x + qy * c.y + qz * c.z;                            \
        float d2 = qs + cs2 - 2.0f * dot;                                      \
        unsigned long long key =                                               \
            ((unsigned long long)ord_f32(d2) << 32) |                          \
            (uint32_t)__float_as_int(c.w);                                     \
        if (key < bk[KNN - 1]) {                                               \
            unsigned long long cd = key;                                       \
            _Pragma("unroll")                                                  \
            for (int s = 0; s < KNN; s++) {                                    \
                if (cd < bk[s]) {                                              \
                    unsigned long long t = bk[s]; bk[s] = cd; cd = t;          \
                }                                                              \
            }                                                                  \
        }                                                                      \
    }

__global__ __launch_bounds__(256) void knn_grid_kernel(const float* __restrict__ coords) {
    __shared__ unsigned long long mk[KQPB][TPQ][KNN];   // 32 KB

    const int tid  = threadIdx.x;
    const int ql   = tid >> 3;      // query within block
    const int g    = tid & 7;       // sub-scanner
    const int lane = tid & 31;
    const unsigned grpmask = 0xFFu << (lane & ~7);

    const int sp = blockIdx.x * KQPB + ql;     // sorted position (coherent)
    float4 me = g_sorted[sp];
    const float qx = me.x, qy = me.y, qz = me.z;
    const int q = __float_as_int(me.w);
    const float qs = qx * qx + qy * qy + qz * qz;
    const int cx = cell_coord(qx), cy = cell_coord(qy), cz = cell_coord(qz);

    unsigned long long bk[KNN];
#pragma unroll
    for (int s = 0; s < KNN; s++) bk[s] = 0xFFFFFFFFFFFFFFFFull;

    // ---- r<=1 box: own z-column first, then up to 8 neighbor spans ----
    {
        int z0 = max(cz - 1, 0), z1 = min(cz + 1, GRES - 1);
        int x0 = max(cx - 1, 0), x1 = min(cx + 1, GRES - 1);
        int y0 = max(cy - 1, 0), y1 = min(cy + 1, GRES - 1);
        {
            int rb = (cx * GRES + cy) * GRES;
            int s0 = g_cell_off[rb + z0];
            int e0 = g_cell_off[rb + z1 + 1];
            SCAN_SPAN(s0, e0)
        }
        for (int ix = x0; ix <= x1; ix++) {
            for (int iy = y0; iy <= y1; iy++) {
                if (ix == cx && iy == cy) continue;
                int rb = (ix * GRES + iy) * GRES;
                int s0 = g_cell_off[rb + z0];
                int e0 = g_cell_off[rb + z1 + 1];
                SCAN_SPAN(s0, e0)
            }
        }
    }

    // ---- exact fallback: expand Chebyshev shells r = 2.. ----
    for (int r = 2; r < GRES; r++) {
        uint32_t kmin = (uint32_t)(bk[KNN - 1] >> 32);
        kmin = min(kmin, __shfl_xor_sync(grpmask, kmin, 1));
        kmin = min(kmin, __shfl_xor_sync(grpmask, kmin, 2));
        kmin = min(kmin, __shfl_xor_sync(grpmask, kmin, 4));
        float rr = (float)(r - 1) * CELLSZ;
        uint32_t rru = ord_f32(rr * rr);
        if (kmin < rru) break;
        int zlo = cz - r, zhi = cz + r;
        for (int dx = -r; dx <= r; dx++) {
            int ix = cx + dx;
            if (ix < 0 || ix >= GRES) continue;
            for (int dy = -r; dy <= r; dy++) {
                int iy = cy + dy;
                if (iy < 0 || iy >= GRES) continue;
                int rb = (ix * GRES + iy) * GRES;
                if (max(abs(dx), abs(dy)) == r) {
                    int a0 = max(zlo, 0), a1 = min(zhi, GRES - 1);
                    int s0 = g_cell_off[rb + a0];
                    int e0 = g_cell_off[rb + a1 + 1];
                    SCAN_SPAN(s0, e0)
                } else {
                    if (zlo >= 0) {
                        int s0 = g_cell_off[rb + zlo];
                        int e0 = g_cell_off[rb + zlo + 1];
                        SCAN_SPAN(s0, e0)
                    }
                    if (zhi < GRES) {
                        int s0 = g_cell_off[rb + zhi];
                        int e0 = g_cell_off[rb + zhi + 1];
                        SCAN_SPAN(s0, e0)
                    }
                }
            }
        }
    }

#pragma unroll
    for (int s = 0; s < KNN; s++) mk[ql][g][s] = bk[s];
    __syncwarp(grpmask);

    if (g == 0) {
        int h[TPQ] = {};
        for (int s = 0; s < KNN; s++) {
            unsigned long long best = 0xFFFFFFFFFFFFFFFFull; int bl = 0;
#pragma unroll
            for (int l = 0; l < TPQ; l++) {
                unsigned long long v = mk[ql][l][h[l]];
                if (v < best) { best = v; bl = l; }
            }
            h[bl]++;
            int biv = (int)(uint32_t)best;
            g_idx[q * KNN + s] = biv;
            g_delta[(q * KNN + s) * 3 + 0] = coords[biv * 3 + 0] - qx;
            g_delta[(q * KNN + s) * 3 + 1] = coords[biv * 3 + 1] - qy;
            g_delta[(q * KNN + s) * 3 + 2] = coords[biv * 3 + 2] - qz;
        }
    }
}

// ---------------- tf32 helpers ----------------------------------------------
__device__ __forceinline__ float to_tf32(float x) {
    float r;
    asm("cvt.rna.tf32.f32 %0, %1;" : "=f"(r) : "f"(x));
    return r;
}

#define TA_PAD 36
#define TB_PAD 72

#define MMA_TF32(acc, a, b0, b1)                                               \
    asm volatile(                                                              \
        "mma.sync.aligned.m16n8k8.row.col.f32.tf32.tf32.f32 "                  \
        "{%0,%1,%2,%3}, {%4,%5,%6,%7}, {%8,%9}, {%0,%1,%2,%3};"                \
        : "+f"(acc[0]), "+f"(acc[1]), "+f"(acc[2]), "+f"(acc[3])               \
        : "r"(a[0]), "r"(a[1]), "r"(a[2]), "r"(a[3]), "r"(b0), "r"(b1))

// ---------------- fused theta/phi/g tf32 GEMM -------------------------------
__global__ __launch_bounds__(256) void gemm3_tf32_kernel(
    const float* __restrict__ A,
    const float* __restrict__ B0, const float* __restrict__ B1, const float* __restrict__ B2,
    const float* __restrict__ bias0, const float* __restrict__ bias1, const float* __restrict__ bias2,
    float* __restrict__ C0, float* __restrict__ C1, float* __restrict__ C2)
{
    __shared__ float As[128][TA_PAD];
    __shared__ float Bs[3][32][TB_PAD];

    const int tid  = threadIdx.x;
    const int lane = tid & 31;
    const int wid  = tid >> 5;
    const int warp_m = wid & 3;
    const int warp_n = wid >> 2;
    const int qg = lane & 3;
    const int gr = lane >> 2;

    const int m0 = blockIdx.y * 128;
    const int n0 = blockIdx.x * 64;

    float acc[3][2][4][4] = {};
    const float* Bp[3] = {B0, B1, B2};

    const int ar  = tid >> 1, aseg = tid & 1;
    const int br  = tid >> 3, bseg = tid & 7;

    for (int k0 = 0; k0 < C_DIM; k0 += 32) {
        __syncthreads();
        {
            const float4* src = (const float4*)(A + (size_t)(m0 + ar) * C_DIM + k0 + aseg * 16);
#pragma unroll
            for (int i = 0; i < 4; i++) {
                float4 v = src[i];
                int c = aseg * 16 + i * 4;
                As[ar][c + 0] = to_tf32(v.x); As[ar][c + 1] = to_tf32(v.y);
                As[ar][c + 2] = to_tf32(v.z); As[ar][c + 3] = to_tf32(v.w);
            }
        }
#pragma unroll
        for (int w = 0; w < 3; w++) {
            const float4* src = (const float4*)(Bp[w] + (size_t)(k0 + br) * C_DIM + n0 + bseg * 8);
            float4 v0 = src[0], v1 = src[1];
            int c = bseg * 8;
            Bs[w][br][c + 0] = to_tf32(v0.x); Bs[w][br][c + 1] = to_tf32(v0.y);
            Bs[w][br][c + 2] = to_tf32(v0.z); Bs[w][br][c + 3] = to_tf32(v0.w);
            Bs[w][br][c + 4] = to_tf32(v1.x); Bs[w][br][c + 5] = to_tf32(v1.y);
            Bs[w][br][c + 6] = to_tf32(v1.z); Bs[w][br][c + 7] = to_tf32(v1.w);
        }
        __syncthreads();
#pragma unroll
        for (int kk = 0; kk < 32; kk += 8) {
            uint32_t a[2][4];
#pragma unroll
            for (int mt = 0; mt < 2; mt++) {
                int r = warp_m * 32 + mt * 16 + gr;
                a[mt][0] = __float_as_uint(As[r    ][kk + qg]);
                a[mt][1] = __float_as_uint(As[r + 8][kk + qg]);
                a[mt][2] = __float_as_uint(As[r    ][kk + qg + 4]);
                a[mt][3] = __float_as_uint(As[r + 8][kk + qg + 4]);
            }
#pragma unroll
            for (int w = 0; w < 3; w++) {
#pragma unroll
                for (int nt = 0; nt < 4; nt++) {
                    int n = warp_n * 32 + nt * 8 + gr;
                    uint32_t b0 = __float_as_uint(Bs[w][kk + qg    ][n]);
                    uint32_t b1 = __float_as_uint(Bs[w][kk + qg + 4][n]);
#pragma unroll
                    for (int mt = 0; mt < 2; mt++) MMA_TF32(acc[w][mt][nt], a[mt], b0, b1);
                }
            }
        }
    }
    const float* biasp[3] = {bias0, bias1, bias2};
    float* Cp[3] = {C0, C1, C2};
#pragma unroll
    for (int w = 0; w < 3; w++) {
#pragma unroll
        for (int mt = 0; mt < 2; mt++) {
#pragma unroll
            for (int nt = 0; nt < 4; nt++) {
                int r = warp_m * 32 + mt * 16 + gr;
                int c = warp_n * 32 + nt * 8 + 2 * qg;
                int n = n0 + c;
                float bn0 = biasp[w][n], bn1 = biasp[w][n + 1];
                float2 v0 = make_float2(acc[w][mt][nt][0] + bn0, acc[w][mt][nt][1] + bn1);
                float2 v1 = make_float2(acc[w][mt][nt][2] + bn0, acc[w][mt][nt][3] + bn1);
                *(float2*)(Cp[w] + (size_t)(m0 + r    ) * C_DIM + n) = v0;
                *(float2*)(Cp[w] + (size_t)(m0 + r + 8) * C_DIM + n) = v1;
            }
        }
    }
}

// ---------------- tf32 GEMM with bias + residual (final W layer) ------------
__global__ __launch_bounds__(256) void gemm_tf32_resid_kernel(
    const float* __restrict__ A, const float* __restrict__ B,
    const float* __restrict__ bias, const float* __restrict__ resid,
    float* __restrict__ Cout)
{
    __shared__ float As[128][TA_PAD];
    __shared__ float Bs[32][TB_PAD];

    const int tid  = threadIdx.x;
    const int lane = tid & 31;
    const int wid  = tid >> 5;
    const int warp_m = wid & 3;
    const int warp_n = wid >> 2;
    const int qg = lane & 3;
    const int gr = lane >> 2;

    const int m0 = blockIdx.y * 128;
    const int n0 = blockIdx.x * 64;

    float acc[2][4][4] = {};

    const int ar  = tid >> 1, aseg = tid & 1;
    const int br  = tid >> 3, bseg = tid & 7;

    for (int k0 = 0; k0 < C_DIM; k0 += 32) {
        __syncthreads();
        {
            const float4* src = (const float4*)(A + (size_t)(m0 + ar) * C_DIM + k0 + aseg * 16);
#pragma unroll
            for (int i = 0; i < 4; i++) {
                float4 v = src[i];
                int c = aseg * 16 + i * 4;
                As[ar][c + 0] = to_tf32(v.x); As[ar][c + 1] = to_tf32(v.y);
                As[ar][c + 2] = to_tf32(v.z); As[ar][c + 3] = to_tf32(v.w);
            }
        }
        {
            const float4* src = (const float4*)(B + (size_t)(k0 + br) * C_DIM + n0 + bseg * 8);
            float4 v0 = src[0], v1 = src[1];
            int c = bseg * 8;
            Bs[br][c + 0] = to_tf32(v0.x); Bs[br][c + 1] = to_tf32(v0.y);
            Bs[br][c + 2] = to_tf32(v0.z); Bs[br][c + 3] = to_tf32(v0.w);
            Bs[br][c + 4] = to_tf32(v1.x); Bs[br][c + 5] = to_tf32(v1.y);
            Bs[br][c + 6] = to_tf32(v1.z); Bs[br][c + 7] = to_tf32(v1.w);
        }
        __syncthreads();
#pragma unroll
        for (int kk = 0; kk < 32; kk += 8) {
            uint32_t a[2][4];
#pragma unroll
            for (int mt = 0; mt < 2; mt++) {
                int r = warp_m * 32 + mt * 16 + gr;
                a[mt][0] = __float_as_uint(As[r    ][kk + qg]);
                a[mt][1] = __float_as_uint(As[r + 8][kk + qg]);
                a[mt][2] = __float_as_uint(As[r    ][kk + qg + 4]);
                a[mt][3] = __float_as_uint(As[r + 8][kk + qg + 4]);
            }
#pragma unroll
            for (int nt = 0; nt < 4; nt++) {
                int n = warp_n * 32 + nt * 8 + gr;
                uint32_t b0 = __float_as_uint(Bs[kk + qg    ][n]);
                uint32_t b1 = __float_as_uint(Bs[kk + qg + 4][n]);
#pragma unroll
                for (int mt = 0; mt < 2; mt++) MMA_TF32(acc[mt][nt], a[mt], b0, b1);
            }
        }
    }
#pragma unroll
    for (int mt = 0; mt < 2; mt++) {
#pragma unroll
        for (int nt = 0; nt < 4; nt++) {
            int r = warp_m * 32 + mt * 16 + gr;
            int c = warp_n * 32 + nt * 8 + 2 * qg;
            int n = n0 + c;
            float bn0 = bias[n], bn1 = bias[n + 1];
            float2 r0 = *(const float2*)(resid + (size_t)(m0 + r    ) * C_DIM + n);
            float2 r1 = *(const float2*)(resid + (size_t)(m0 + r + 8) * C_DIM + n);
            float2 v0 = make_float2(acc[mt][nt][0] + bn0 + r0.x, acc[mt][nt][1] + bn1 + r0.y);
            float2 v1 = make_float2(acc[mt][nt][2] + bn0 + r1.x, acc[mt][nt][3] + bn1 + r1.y);
            *(float2*)(Cout + (size_t)(m0 + r    ) * C_DIM + n) = v0;
            *(float2*)(Cout + (size_t)(m0 + r + 8) * C_DIM + n) = v1;
        }
    }
}

// ---------------- prep: w2 -> bf16 transposed --------------------------------
__global__ void w2_prep_kernel(const float* __restrict__ w2) {
    int t = blockIdx.x * blockDim.x + threadIdx.x;
    int n = t >> 8, k = t & 255;
    g_w2t[n * C_DIM + k] = __float2bfloat16(w2[k * C_DIM + n]);
}

// ---------------- pe_attn v4: ldmatrix frag loads + double-buffered B -------
#define A_STRIDE 264   // bf16 elems; 528 B = 33*16 (LDSM-aligned), 132w%32==4
#define B_STRIDE 72    // bf16 elems; 144 B = 9*16,  36w%32==4
#define C_STRIDE 260   // fp32 words
#define B_BUF_ELEMS (256 * B_STRIDE)                      // 18432 bf16 per buffer
#define SMEM_A_BYTES (128 * A_STRIDE * 2)                 // 67584
#define SMEM_B_BYTES (2 * B_BUF_ELEMS * 2)                // 73728 (double buffer)
#define SMEM_DS_OFF  (SMEM_A_BYTES + SMEM_B_BYTES)        // 141312
#define SMEM_IDX_OFF (SMEM_DS_OFF + 128 * 3 * 4)          // 142848
#define SMEM_TOTAL_PE (SMEM_IDX_OFF + 128 * 4)            // 143360
// Cs (128*260*4 = 133120) overlays A+B start; ds/idx live above it.

#define MMA_BF16(acc, a, b0, b1)                                               \
    asm volatile(                                                              \
        "mma.sync.aligned.m16n8k16.row.col.f32.bf16.bf16.f32 "                 \
        "{%0,%1,%2,%3}, {%4,%5,%6,%7}, {%8,%9}, {%0,%1,%2,%3};"                \
        : "+f"(acc[0]), "+f"(acc[1]), "+f"(acc[2]), "+f"(acc[3])               \
        : "r"(a[0]), "r"(a[1]), "r"(a[2]), "r"(a[3]), "r"(b0), "r"(b1))

#define LDSM_X4(r0, r1, r2, r3, addr)                                          \
    asm volatile(                                                              \
        "ldmatrix.sync.aligned.m8n8.x4.shared.b16 {%0,%1,%2,%3}, [%4];"        \
        : "=r"(r0), "=r"(r1), "=r"(r2), "=r"(r3) : "r"(addr))

__global__ __launch_bounds__(512, 1) void pe_attn3_kernel(
    const float* __restrict__ w1, const float* __restrict__ b1,
    const float* __restrict__ b2)
{
    extern __shared__ __align__(16) char sm[];
    __nv_bfloat16* Asm = (__nv_bfloat16*)sm;
    __nv_bfloat16* Bsm = (__nv_bfloat16*)(sm + SMEM_A_BYTES);
    float* Cs   = (float*)sm;                      // union over A+B after mainloop
    float* ds   = (float*)(sm + SMEM_DS_OFF);
    int*   idxs = (int*)(sm + SMEM_IDX_OFF);

    const int tid  = threadIdx.x;
    const int lane = tid & 31;
    const int wid  = tid >> 5;
    const int warp_m = wid & 3;      // 4 x 32 rows
    const int warp_n = wid >> 2;     // 4 x 64 cols
    const int qg = lane & 3;
    const int gr = lane >> 2;

    const int m0  = blockIdx.x * 128;
    const int pt0 = blockIdx.x * 8;

    if (tid < 384) ds[tid] = g_delta[(size_t)m0 * 3 + tid];
    if (tid < 128) idxs[tid] = g_idx[pt0 * KNN + tid];
    __syncthreads();

    const int bn = tid >> 1, bh = tid & 1;   // B chunk load mapping

    // ---- A-gen once + B chunk 0 load, then one sync ----
    {
        int jj = tid & 255, rh = tid >> 8;
        float wa = w1[jj], wb = w1[C_DIM + jj], wc = w1[2 * C_DIM + jj];
        float bb = b1[jj];
#pragma unroll 8
        for (int i = 0; i < 64; i++) {
            int r = rh * 64 + i;
            float h = fmaf(ds[r * 3 + 0], wa,
                      fmaf(ds[r * 3 + 1], wb,
                      fmaf(ds[r * 3 + 2], wc, bb)));
            Asm[r * A_STRIDE + jj] = __float2bfloat16(fmaxf(h, 0.0f));
        }
    }
    {
        const uint4* src = (const uint4*)(g_w2t + (size_t)bn * C_DIM + bh * 32);
        uint4* dst = (uint4*)(Bsm + bn * B_STRIDE + bh * 32);
        dst[0] = src[0]; dst[1] = src[1]; dst[2] = src[2]; dst[3] = src[3];
    }
    __syncthreads();

    // ---- ldmatrix base addresses (byte offsets fixed per lane) ----
    const int a_row = (lane & 7) + (lane & 8);         // 0..15
    const int a_col = (lane >> 4) * 8;                 // 0 or 8
    uint32_t a_base[2];
#pragma unroll
    for (int mt = 0; mt < 2; mt++)
        a_base[mt] = (uint32_t)__cvta_generic_to_shared(
            Asm + (warp_m * 32 + mt * 16 + a_row) * A_STRIDE + a_col);
    const int b_rowl = (lane >> 4);                    // nt sub-select
    const int b_coll = ((lane >> 3) & 1) * 8;          // k half
    uint32_t b_base[4];
#pragma unroll
    for (int p = 0; p < 4; p++) {
        int nrow = warp_n * 64 + (2 * p + b_rowl) * 8 + (lane & 7);
        b_base[p] = (uint32_t)__cvta_generic_to_shared(
            Bsm + nrow * B_STRIDE + b_coll);
    }

    float acc[2][8][4] = {};

    for (int c0 = 0; c0 < 4; c0++) {
        // prefetch next B chunk into the other buffer (overlaps with MMA)
        if (c0 < 3) {
            const uint4* src = (const uint4*)(g_w2t + (size_t)bn * C_DIM + (c0 + 1) * 64 + bh * 32);
            uint4* dst = (uint4*)(Bsm + ((c0 + 1) & 1) * B_BUF_ELEMS + bn * B_STRIDE + bh * 32);
            dst[0] = src[0]; dst[1] = src[1]; dst[2] = src[2]; dst[3] = src[3];
        }
        const uint32_t bufoff = (uint32_t)((c0 & 1) * B_BUF_ELEMS * 2);
#pragma unroll
        for (int kk = 0; kk < 64; kk += 16) {
            const int ka = c0 * 64 + kk;
            uint32_t a[2][4];
            LDSM_X4(a[0][0], a[0][1], a[0][2], a[0][3], a_base[0] + (uint32_t)(ka * 2));
            LDSM_X4(a[1][0], a[1][1], a[1][2], a[1][3], a_base[1] + (uint32_t)(ka * 2));
#pragma unroll
            for (int p = 0; p < 4; p++) {
                uint32_t b0, b1r, b2, b3;
                LDSM_X4(b0, b1r, b2, b3, b_base[p] + bufoff + (uint32_t)(kk * 2));
                MMA_BF16(acc[0][2 * p    ], a[0], b0, b1r);
                MMA_BF16(acc[1][2 * p    ], a[1], b0, b1r);
                MMA_BF16(acc[0][2 * p + 1], a[0], b2, b3);
                MMA_BF16(acc[1][2 * p + 1], a[1], b2, b3);
            }
        }
        __syncthreads();   // next buffer ready; current buffer reads done
    }

    // ---- overlay Cs and dump (all warps past mainloop) ----
#pragma unroll
    for (int mt = 0; mt < 2; mt++) {
#pragma unroll
        for (int nt = 0; nt < 8; nt++) {
            int r = warp_m * 32 + mt * 16 + gr;
            int c = warp_n * 64 + nt * 8 + 2 * qg;
            Cs[(r    ) * C_STRIDE + c    ] = acc[mt][nt][0];
            Cs[(r    ) * C_STRIDE + c + 1] = acc[mt][nt][1];
            Cs[(r + 8) * C_STRIDE + c    ] = acc[mt][nt][2];
            Cs[(r + 8) * C_STRIDE + c + 1] = acc[mt][nt][3];
        }
    }
    __syncthreads();

    // ---- per-thread softmax epilogue ----
    {
        int p  = tid >> 6;
        int cb = tid & 63;
        int n_pt = pt0 + p;
#pragma unroll
        for (int cc = 0; cc < 4; cc++) {
            int c = cb + cc * 64;
            float tv = g_theta[(size_t)n_pt * C_DIM + c];
            float bb = b2[c];
            float df[KNN];
            float mx = -3.4e38f;
#pragma unroll
            for (int k = 0; k < KNN; k++) {
                int j = idxs[p * KNN + k];
                float ph = g_phi[(size_t)j * C_DIM + c];
                float pe = Cs[(p * KNN + k) * C_STRIDE + c] + bb;
                float v = pe * (tv - ph + 1.0f) * 0.0625f;
                df[k] = v;
                mx = fmaxf(mx, v);
            }
            float s = 0.0f;
#pragma unroll
            for (int k = 0; k < KNN; k++) { df[k] = __expf(df[k] - mx); s += df[k]; }
            float inv = 1.0f / s;
            float y = 0.0f;
#pragma unroll
            for (int k = 0; k < KNN; k++) {
                int j = idxs[p * KNN + k];
                y = fmaf(df[k] * inv, g_gf[(size_t)j * C_DIM + c], y);
            }
            g_y[(size_t)n_pt * C_DIM + c] = y;
        }
    }
}

// ---------------- launch ----------------------------------------------------
static cudaStream_t s_gemm = nullptr, s_prep = nullptr;
static cudaEvent_t  ev_fork = nullptr, ev_gemm = nullptr, ev_prep = nullptr;

extern "C" void kernel_launch(void* const* d_in, const int* in_sizes, int n_in,
                              void* d_out, int out_size) {
    const float* coords  = (const float*)d_in[0];
    const float* feats   = (const float*)d_in[1];
    const float* theta_w = (const float*)d_in[2];
    const float* theta_b = (const float*)d_in[3];
    const float* phi_w   = (const float*)d_in[4];
    const float* phi_b   = (const float*)d_in[5];
    const float* g_w     = (const float*)d_in[6];
    const float* g_b     = (const float*)d_in[7];
    const float* pe1_w1  = (const float*)d_in[8];
    const float* pe1_b1  = (const float*)d_in[9];
    const float* pe1_w2  = (const float*)d_in[10];
    const float* pe1_b2  = (const float*)d_in[11];
    const float* W_w     = (const float*)d_in[12];
    const float* W_b     = (const float*)d_in[13];
    float* out = (float*)d_out;

    if (!s_gemm) {
        cudaStreamCreateWithFlags(&s_gemm, cudaStreamNonBlocking);
        cudaStreamCreateWithFlags(&s_prep, cudaStreamNonBlocking);
        cudaEventCreateWithFlags(&ev_fork, cudaEventDisableTiming);
        cudaEventCreateWithFlags(&ev_gemm, cudaEventDisableTiming);
        cudaEventCreateWithFlags(&ev_prep, cudaEventDisableTiming);
    }

    float *p_theta, *p_phi, *p_gf, *p_y;
    cudaGetSymbolAddress((void**)&p_theta, g_theta);
    cudaGetSymbolAddress((void**)&p_phi,   g_phi);
    cudaGetSymbolAddress((void**)&p_gf,    g_gf);
    cudaGetSymbolAddress((void**)&p_y,     g_y);

    cudaFuncSetAttribute(pe_attn3_kernel,
                         cudaFuncAttributeMaxDynamicSharedMemorySize, SMEM_TOTAL_PE);

    // fork point: side-stream work depends only on pre-chain state
    cudaEventRecord(ev_fork, 0);
    cudaStreamWaitEvent(s_gemm, ev_fork, 0);
    cudaStreamWaitEvent(s_prep, ev_fork, 0);

    // main stream: grid KNN chain (knn_grid is the 4th kernel launch -> profiled)
    cell_count_kernel<<<N_PTS / 256, 256>>>(coords);
    cell_scan_kernel<<<1, 512>>>();                       // also re-zeroes counts
    cell_scatter_kernel<<<N_PTS / 256, 256>>>(coords);
    knn_grid_kernel<<<N_PTS / KQPB, 256>>>(coords);

    // forked work (runs concurrently with the KNN chain)
    dim3 gt(C_DIM / 64, N_PTS / 128);   // (4, 64)
    gemm3_tf32_kernel<<<gt, 256, 0, s_gemm>>>(feats, theta_w, phi_w, g_w,
                                              theta_b, phi_b, g_b,
                                              p_theta, p_phi, p_gf);
    cudaEventRecord(ev_gemm, s_gemm);

    w2_prep_kernel<<<C_DIM * C_DIM / 256, 256, 0, s_prep>>>(pe1_w2);
    cudaEventRecord(ev_prep, s_prep);

    // join
    cudaStreamWaitEvent(0, ev_gemm, 0);
    cudaStreamWaitEvent(0, ev_prep, 0);

    pe_attn3_kernel<<<N_PTS * KNN / 128, 512, SMEM_TOTAL_PE>>>(pe1_w1, pe1_b1, pe1_b2);

    gemm_tf32_resid_kernel<<<gt, 256>>>(p_y, W_w, W_b, feats, out);
}

// round 16
// speedup vs baseline: 1.3887x; 1.3887x over previous
#include <cuda_runtime.h>
#include <cuda_bf16.h>
#include <math.h>
#include <stdint.h>

#define N_PTS 8192
#define C_DIM 256
#define KNN   16

// ---------------- scratch (device globals; no allocations allowed) ----------
__device__ int   g_idx[N_PTS * KNN];
__device__ float g_delta[N_PTS * KNN * 3];
__device__ float g_theta[N_PTS * C_DIM];
__device__ float g_phi[N_PTS * C_DIM];
__device__ float g_gf[N_PTS * C_DIM];
__device__ float g_y[N_PTS * C_DIM];
__device__ __nv_bfloat16 g_w2t[C_DIM * C_DIM];   // w2 transposed, bf16: [n][k]

// ---------------- grid-KNN scratch (grid: 10^3, cell = 10.0) ----------------
#define GRES   10
#define NCELLS (GRES * GRES * GRES)          // 1000
#define CELLSZ 10.0f
__device__ int    g_cell_cnt[NCELLS];        // zero-init at load; scan re-zeroes
__device__ int    g_cell_off[NCELLS + 1];
__device__ int    g_cell_cur[NCELLS];
__device__ float4 g_sorted[N_PTS];           // (x, y, z, bitcast orig idx)

__device__ __forceinline__ int cell_coord(float x) {
    int c = (int)(x * 0.1f);                 // 10 / 100
    return min(GRES - 1, max(0, c));
}

__global__ void cell_count_kernel(const float* __restrict__ coords) {
    int q = blockIdx.x * 256 + threadIdx.x;
    int cx = cell_coord(coords[q * 3 + 0]);
    int cy = cell_coord(coords[q * 3 + 1]);
    int cz = cell_coord(coords[q * 3 + 2]);
    atomicAdd(&g_cell_cnt[(cx * GRES + cy) * GRES + cz], 1);
}

// single block, 512 threads, 2 cells each: exclusive prefix sum over 1000.
// Also re-zeroes g_cell_cnt for the next graph replay (self-restoring state).
__global__ void cell_scan_kernel() {
    __shared__ int part[512];
    int t = threadIdx.x;
    int c0 = 2 * t, c1 = 2 * t + 1;
    int v0 = (c0 < NCELLS) ? g_cell_cnt[c0] : 0;
    int v1 = (c1 < NCELLS) ? g_cell_cnt[c1] : 0;
    if (c0 < NCELLS) g_cell_cnt[c0] = 0;
    if (c1 < NCELLS) g_cell_cnt[c1] = 0;
    int s = v0 + v1;
    part[t] = s;
    __syncthreads();
    for (int off = 1; off < 512; off <<= 1) {
        int u = (t >= off) ? part[t - off] : 0;
        __syncthreads();
        part[t] += u;
        __syncthreads();
    }
    int excl = part[t] - s;
    if (c0 < NCELLS) { g_cell_off[c0] = excl;      g_cell_cur[c0] = excl; }
    if (c1 < NCELLS) { g_cell_off[c1] = excl + v0; g_cell_cur[c1] = excl + v0; }
    if (t == 511) g_cell_off[NCELLS] = part[511];
}

__global__ void cell_scatter_kernel(const float* __restrict__ coords) {
    int q = blockIdx.x * 256 + threadIdx.x;
    float x = coords[q * 3 + 0], y = coords[q * 3 + 1], z = coords[q * 3 + 2];
    int cell = (cell_coord(x) * GRES + cell_coord(y)) * GRES + cell_coord(z);
    int pos = atomicAdd(&g_cell_cur[cell], 1);
    g_sorted[pos] = make_float4(x, y, z, __int_as_float(q));
}

// ---------------- grid KNN v6: u64 keys, 4 threads/query, GRES=10 -----------
// key = (ordered(d2) << 32) | idx; integer order == lexicographic (d2, idx)
// == jax.lax.top_k stable order. Structure identical to the R14-proven
// TPQ=4 kernel; only the grid resolution changed (half the candidates; stop
// threshold after the r<=1 box is CELLSZ^2=100 >> typical r16^2~60).
#define TPQ  4
#define KQPB 64    // queries per block (256 threads / 4)

__device__ __forceinline__ uint32_t ord_f32(float f) {
    uint32_t u = __float_as_uint(f);
    u ^= (uint32_t)((int)u >> 31) | 0x80000000u;
    return u;
}

#define SCAN_SPAN(S, E)                                                        \
    for (int p = (S) + g; p < (E); p += TPQ) {                                 \
        float4 c = g_sorted[p];                                                \
        float cs2 = c.x * c.x + c.y * c.y + c.z * c.z;                         \
        float dot = qx * c.x + qy * c.y + qz * c.z;                            \
        float d2 = qs + cs2 - 2.0f * dot;                                      \
        unsigned long long key =                                               \
            ((unsigned long long)ord_f32(d2) << 32) |                          \
            (uint32_t)__float_as_int(c.w);                                     \
        if (key < bk[KNN - 1]) {                                               \
            unsigned long long cd = key;                                       \
            _Pragma("unroll")                                                  \
            for (int s = 0; s < KNN; s++) {                                    \
                if (cd < bk[s]) {                                              \
                    unsigned long long t = bk[s]; bk[s] = cd; cd = t;          \
                }                                                              \
            }                                                                  \
        }                                                                      \
    }

__global__ __launch_bounds__(256) void knn_grid_kernel(const float* __restrict__ coords) {
    __shared__ unsigned long long mk[KQPB][TPQ][KNN];   // 32 KB

    const int tid  = threadIdx.x;
    const int ql   = tid >> 2;      // query within block
    const int g    = tid & 3;       // sub-scanner
    const int lane = tid & 31;
    const unsigned grpmask = 0xFu << (lane & ~3);

    const int sp = blockIdx.x * KQPB + ql;     // sorted position (coherent)
    float4 me = g_sorted[sp];
    const float qx = me.x, qy = me.y, qz = me.z;
    const int q = __float_as_int(me.w);
    const float qs = qx * qx + qy * qy + qz * qz;
    const int cx = cell_coord(qx), cy = cell_coord(qy), cz = cell_coord(qz);

    unsigned long long bk[KNN];
#pragma unroll
    for (int s = 0; s < KNN; s++) bk[s] = 0xFFFFFFFFFFFFFFFFull;

    // ---- r<=1 box: own z-column first, then up to 8 neighbor spans ----
    {
        int z0 = max(cz - 1, 0), z1 = min(cz + 1, GRES - 1);
        int x0 = max(cx - 1, 0), x1 = min(cx + 1, GRES - 1);
        int y0 = max(cy - 1, 0), y1 = min(cy + 1, GRES - 1);
        {
            int rb = (cx * GRES + cy) * GRES;
            int s0 = g_cell_off[rb + z0];
            int e0 = g_cell_off[rb + z1 + 1];
            SCAN_SPAN(s0, e0)
        }
        for (int ix = x0; ix <= x1; ix++) {
            for (int iy = y0; iy <= y1; iy++) {
                if (ix == cx && iy == cy) continue;
                int rb = (ix * GRES + iy) * GRES;
                int s0 = g_cell_off[rb + z0];
                int e0 = g_cell_off[rb + z1 + 1];
                SCAN_SPAN(s0, e0)
            }
        }
    }

    // ---- exact fallback: expand Chebyshev shells r = 2.. ----
    for (int r = 2; r < GRES; r++) {
        uint32_t kmin = (uint32_t)(bk[KNN - 1] >> 32);
        kmin = min(kmin, __shfl_xor_sync(grpmask, kmin, 1));
        kmin = min(kmin, __shfl_xor_sync(grpmask, kmin, 2));
        float rr = (float)(r - 1) * CELLSZ;
        uint32_t rru = ord_f32(rr * rr);
        if (kmin < rru) break;
        int zlo = cz - r, zhi = cz + r;
        for (int dx = -r; dx <= r; dx++) {
            int ix = cx + dx;
            if (ix < 0 || ix >= GRES) continue;
            for (int dy = -r; dy <= r; dy++) {
                int iy = cy + dy;
                if (iy < 0 || iy >= GRES) continue;
                int rb = (ix * GRES + iy) * GRES;
                if (max(abs(dx), abs(dy)) == r) {
                    int a0 = max(zlo, 0), a1 = min(zhi, GRES - 1);
                    int s0 = g_cell_off[rb + a0];
                    int e0 = g_cell_off[rb + a1 + 1];
                    SCAN_SPAN(s0, e0)
                } else {
                    if (zlo >= 0) {
                        int s0 = g_cell_off[rb + zlo];
                        int e0 = g_cell_off[rb + zlo + 1];
                        SCAN_SPAN(s0, e0)
                    }
                    if (zhi < GRES) {
                        int s0 = g_cell_off[rb + zhi];
                        int e0 = g_cell_off[rb + zhi + 1];
                        SCAN_SPAN(s0, e0)
                    }
                }
            }
        }
    }

#pragma unroll
    for (int s = 0; s < KNN; s++) mk[ql][g][s] = bk[s];
    __syncwarp(grpmask);

    if (g == 0) {
        int h[TPQ] = {};
        for (int s = 0; s < KNN; s++) {
            unsigned long long best = 0xFFFFFFFFFFFFFFFFull; int bl = 0;
#pragma unroll
            for (int l = 0; l < TPQ; l++) {
                unsigned long long v = mk[ql][l][h[l]];
                if (v < best) { best = v; bl = l; }
            }
            h[bl]++;
            int biv = (int)(uint32_t)best;
            g_idx[q * KNN + s] = biv;
            g_delta[(q * KNN + s) * 3 + 0] = coords[biv * 3 + 0] - qx;
            g_delta[(q * KNN + s) * 3 + 1] = coords[biv * 3 + 1] - qy;
            g_delta[(q * KNN + s) * 3 + 2] = coords[biv * 3 + 2] - qz;
        }
    }
}

// ---------------- tf32 helpers ----------------------------------------------
__device__ __forceinline__ float to_tf32(float x) {
    float r;
    asm("cvt.rna.tf32.f32 %0, %1;" : "=f"(r) : "f"(x));
    return r;
}

#define TA_PAD 36
#define TB_PAD 72

#define MMA_TF32(acc, a, b0, b1)                                               \
    asm volatile(                                                              \
        "mma.sync.aligned.m16n8k8.row.col.f32.tf32.tf32.f32 "                  \
        "{%0,%1,%2,%3}, {%4,%5,%6,%7}, {%8,%9}, {%0,%1,%2,%3};"                \
        : "+f"(acc[0]), "+f"(acc[1]), "+f"(acc[2]), "+f"(acc[3])               \
        : "r"(a[0]), "r"(a[1]), "r"(a[2]), "r"(a[3]), "r"(b0), "r"(b1))

// ---------------- fused theta/phi/g tf32 GEMM -------------------------------
__global__ __launch_bounds__(256) void gemm3_tf32_kernel(
    const float* __restrict__ A,
    const float* __restrict__ B0, const float* __restrict__ B1, const float* __restrict__ B2,
    const float* __restrict__ bias0, const float* __restrict__ bias1, const float* __restrict__ bias2,
    float* __restrict__ C0, float* __restrict__ C1, float* __restrict__ C2)
{
    __shared__ float As[128][TA_PAD];
    __shared__ float Bs[3][32][TB_PAD];

    const int tid  = threadIdx.x;
    const int lane = tid & 31;
    const int wid  = tid >> 5;
    const int warp_m = wid & 3;
    const int warp_n = wid >> 2;
    const int qg = lane & 3;
    const int gr = lane >> 2;

    const int m0 = blockIdx.y * 128;
    const int n0 = blockIdx.x * 64;

    float acc[3][2][4][4] = {};
    const float* Bp[3] = {B0, B1, B2};

    const int ar  = tid >> 1, aseg = tid & 1;
    const int br  = tid >> 3, bseg = tid & 7;

    for (int k0 = 0; k0 < C_DIM; k0 += 32) {
        __syncthreads();
        {
            const float4* src = (const float4*)(A + (size_t)(m0 + ar) * C_DIM + k0 + aseg * 16);
#pragma unroll
            for (int i = 0; i < 4; i++) {
                float4 v = src[i];
                int c = aseg * 16 + i * 4;
                As[ar][c + 0] = to_tf32(v.x); As[ar][c + 1] = to_tf32(v.y);
                As[ar][c + 2] = to_tf32(v.z); As[ar][c + 3] = to_tf32(v.w);
            }
        }
#pragma unroll
        for (int w = 0; w < 3; w++) {
            const float4* src = (const float4*)(Bp[w] + (size_t)(k0 + br) * C_DIM + n0 + bseg * 8);
            float4 v0 = src[0], v1 = src[1];
            int c = bseg * 8;
            Bs[w][br][c + 0] = to_tf32(v0.x); Bs[w][br][c + 1] = to_tf32(v0.y);
            Bs[w][br][c + 2] = to_tf32(v0.z); Bs[w][br][c + 3] = to_tf32(v0.w);
            Bs[w][br][c + 4] = to_tf32(v1.x); Bs[w][br][c + 5] = to_tf32(v1.y);
            Bs[w][br][c + 6] = to_tf32(v1.z); Bs[w][br][c + 7] = to_tf32(v1.w);
        }
        __syncthreads();
#pragma unroll
        for (int kk = 0; kk < 32; kk += 8) {
            uint32_t a[2][4];
#pragma unroll
            for (int mt = 0; mt < 2; mt++) {
                int r = warp_m * 32 + mt * 16 + gr;
                a[mt][0] = __float_as_uint(As[r    ][kk + qg]);
                a[mt][1] = __float_as_uint(As[r + 8][kk + qg]);
                a[mt][2] = __float_as_uint(As[r    ][kk + qg + 4]);
                a[mt][3] = __float_as_uint(As[r + 8][kk + qg + 4]);
            }
#pragma unroll
            for (int w = 0; w < 3; w++) {
#pragma unroll
                for (int nt = 0; nt < 4; nt++) {
                    int n = warp_n * 32 + nt * 8 + gr;
                    uint32_t b0 = __float_as_uint(Bs[w][kk + qg    ][n]);
                    uint32_t b1 = __float_as_uint(Bs[w][kk + qg + 4][n]);
#pragma unroll
                    for (int mt = 0; mt < 2; mt++) MMA_TF32(acc[w][mt][nt], a[mt], b0, b1);
                }
            }
        }
    }
    const float* biasp[3] = {bias0, bias1, bias2};
    float* Cp[3] = {C0, C1, C2};
#pragma unroll
    for (int w = 0; w < 3; w++) {
#pragma unroll
        for (int mt = 0; mt < 2; mt++) {
#pragma unroll
            for (int nt = 0; nt < 4; nt++) {
                int r = warp_m * 32 + mt * 16 + gr;
                int c = warp_n * 32 + nt * 8 + 2 * qg;
                int n = n0 + c;
                float bn0 = biasp[w][n], bn1 = biasp[w][n + 1];
                float2 v0 = make_float2(acc[w][mt][nt][0] + bn0, acc[w][mt][nt][1] + bn1);
                float2 v1 = make_float2(acc[w][mt][nt][2] + bn0, acc[w][mt][nt][3] + bn1);
                *(float2*)(Cp[w] + (size_t)(m0 + r    ) * C_DIM + n) = v0;
                *(float2*)(Cp[w] + (size_t)(m0 + r + 8) * C_DIM + n) = v1;
            }
        }
    }
}

// ---------------- tf32 GEMM with bias + residual (final W layer) ------------
__global__ __launch_bounds__(256) void gemm_tf32_resid_kernel(
    const float* __restrict__ A, const float* __restrict__ B,
    const float* __restrict__ bias, const float* __restrict__ resid,
    float* __restrict__ Cout)
{
    __shared__ float As[128][TA_PAD];
    __shared__ float Bs[32][TB_PAD];

    const int tid  = threadIdx.x;
    const int lane = tid & 31;
    const int wid  = tid >> 5;
    const int warp_m = wid & 3;
    const int warp_n = wid >> 2;
    const int qg = lane & 3;
    const int gr = lane >> 2;

    const int m0 = blockIdx.y * 128;
    const int n0 = blockIdx.x * 64;

    float acc[2][4][4] = {};

    const int ar  = tid >> 1, aseg = tid & 1;
    const int br  = tid >> 3, bseg = tid & 7;

    for (int k0 = 0; k0 < C_DIM; k0 += 32) {
        __syncthreads();
        {
            const float4* src = (const float4*)(A + (size_t)(m0 + ar) * C_DIM + k0 + aseg * 16);
#pragma unroll
            for (int i = 0; i < 4; i++) {
                float4 v = src[i];
                int c = aseg * 16 + i * 4;
                As[ar][c + 0] = to_tf32(v.x); As[ar][c + 1] = to_tf32(v.y);
                As[ar][c + 2] = to_tf32(v.z); As[ar][c + 3] = to_tf32(v.w);
            }
        }
        {
            const float4* src = (const float4*)(B + (size_t)(k0 + br) * C_DIM + n0 + bseg * 8);
            float4 v0 = src[0], v1 = src[1];
            int c = bseg * 8;
            Bs[br][c + 0] = to_tf32(v0.x); Bs[br][c + 1] = to_tf32(v0.y);
            Bs[br][c + 2] = to_tf32(v0.z); Bs[br][c + 3] = to_tf32(v0.w);
            Bs[br][c + 4] = to_tf32(v1.x); Bs[br][c + 5] = to_tf32(v1.y);
            Bs[br][c + 6] = to_tf32(v1.z); Bs[br][c + 7] = to_tf32(v1.w);
        }
        __syncthreads();
#pragma unroll
        for (int kk = 0; kk < 32; kk += 8) {
            uint32_t a[2][4];
#pragma unroll
            for (int mt = 0; mt < 2; mt++) {
                int r = warp_m * 32 + mt * 16 + gr;
                a[mt][0] = __float_as_uint(As[r    ][kk + qg]);
                a[mt][1] = __float_as_uint(As[r + 8][kk + qg]);
                a[mt][2] = __float_as_uint(As[r    ][kk + qg + 4]);
                a[mt][3] = __float_as_uint(As[r + 8][kk + qg + 4]);
            }
#pragma unroll
            for (int nt = 0; nt < 4; nt++) {
                int n = warp_n * 32 + nt * 8 + gr;
                uint32_t b0 = __float_as_uint(Bs[kk + qg    ][n]);
                uint32_t b1 = __float_as_uint(Bs[kk + qg + 4][n]);
#pragma unroll
                for (int mt = 0; mt < 2; mt++) MMA_TF32(acc[mt][nt], a[mt], b0, b1);
            }
        }
    }
#pragma unroll
    for (int mt = 0; mt < 2; mt++) {
#pragma unroll
        for (int nt = 0; nt < 4; nt++) {
            int r = warp_m * 32 + mt * 16 + gr;
            int c = warp_n * 32 + nt * 8 + 2 * qg;
            int n = n0 + c;
            float bn0 = bias[n], bn1 = bias[n + 1];
            float2 r0 = *(const float2*)(resid + (size_t)(m0 + r    ) * C_DIM + n);
            float2 r1 = *(const float2*)(resid + (size_t)(m0 + r + 8) * C_DIM + n);
            float2 v0 = make_float2(acc[mt][nt][0] + bn0 + r0.x, acc[mt][nt][1] + bn1 + r0.y);
            float2 v1 = make_float2(acc[mt][nt][2] + bn0 + r1.x, acc[mt][nt][3] + bn1 + r1.y);
            *(float2*)(Cout + (size_t)(m0 + r    ) * C_DIM + n) = v0;
            *(float2*)(Cout + (size_t)(m0 + r + 8) * C_DIM + n) = v1;
        }
    }
}

// ---------------- prep: w2 -> bf16 transposed --------------------------------
__global__ void w2_prep_kernel(const float* __restrict__ w2) {
    int t = blockIdx.x * blockDim.x + threadIdx.x;
    int n = t >> 8, k = t & 255;
    g_w2t[n * C_DIM + k] = __float2bfloat16(w2[k * C_DIM + n]);
}

// ---------------- pe_attn v5: ldmatrix mainloop + REGISTER shfl epilogue ----
#define A_STRIDE 264   // bf16 elems; 528 B = 33*16 (LDSM-aligned), 132w%32==4
#define B_STRIDE 72    // bf16 elems; 144 B = 9*16,  36w%32==4
#define B_BUF_ELEMS (256 * B_STRIDE)                      // 18432 bf16 per buffer
#define SMEM_A_BYTES (128 * A_STRIDE * 2)                 // 67584
#define SMEM_B_BYTES (2 * B_BUF_ELEMS * 2)                // 73728 (double buffer)
#define SMEM_DS_OFF  (SMEM_A_BYTES + SMEM_B_BYTES)        // 141312
#define SMEM_IDX_OFF (SMEM_DS_OFF + 128 * 3 * 4)          // 142848
#define SMEM_TOTAL_PE (SMEM_IDX_OFF + 128 * 4)            // 143360

#define MMA_BF16(acc, a, b0, b1)                                               \
    asm volatile(                                                              \
        "mma.sync.aligned.m16n8k16.row.col.f32.bf16.bf16.f32 "                 \
        "{%0,%1,%2,%3}, {%4,%5,%6,%7}, {%8,%9}, {%0,%1,%2,%3};"                \
        : "+f"(acc[0]), "+f"(acc[1]), "+f"(acc[2]), "+f"(acc[3])               \
        : "r"(a[0]), "r"(a[1]), "r"(a[2]), "r"(a[3]), "r"(b0), "r"(b1))

#define LDSM_X4(r0, r1, r2, r3, addr)                                          \
    asm volatile(                                                              \
        "ldmatrix.sync.aligned.m8n8.x4.shared.b16 {%0,%1,%2,%3}, [%4];"        \
        : "=r"(r0), "=r"(r1), "=r"(r2), "=r"(r3) : "r"(addr))

__global__ __launch_bounds__(512, 1) void pe_attn3_kernel(
    const float* __restrict__ w1, const float* __restrict__ b1,
    const float* __restrict__ b2)
{
    extern __shared__ __align__(16) char sm[];
    __nv_bfloat16* Asm = (__nv_bfloat16*)sm;
    __nv_bfloat16* Bsm = (__nv_bfloat16*)(sm + SMEM_A_BYTES);
    float* ds   = (float*)(sm + SMEM_DS_OFF);
    int*   idxs = (int*)(sm + SMEM_IDX_OFF);

    const int tid  = threadIdx.x;
    const int lane = tid & 31;
    const int wid  = tid >> 5;
    const int warp_m = wid & 3;      // 4 x 32 rows
    const int warp_n = wid >> 2;     // 4 x 64 cols
    const int qg = lane & 3;
    const int gr = lane >> 2;

    const int m0  = blockIdx.x * 128;
    const int pt0 = blockIdx.x * 8;

    if (tid < 384) ds[tid] = g_delta[(size_t)m0 * 3 + tid];
    if (tid < 128) idxs[tid] = g_idx[pt0 * KNN + tid];
    __syncthreads();

    const int bn = tid >> 1, bh = tid & 1;   // B chunk load mapping

    // ---- A-gen once + B chunk 0 load, then one sync ----
    {
        int jj = tid & 255, rh = tid >> 8;
        float wa = w1[jj], wb = w1[C_DIM + jj], wc = w1[2 * C_DIM + jj];
        float bb = b1[jj];
#pragma unroll 8
        for (int i = 0; i < 64; i++) {
            int r = rh * 64 + i;
            float h = fmaf(ds[r * 3 + 0], wa,
                      fmaf(ds[r * 3 + 1], wb,
                      fmaf(ds[r * 3 + 2], wc, bb)));
            Asm[r * A_STRIDE + jj] = __float2bfloat16(fmaxf(h, 0.0f));
        }
    }
    {
        const uint4* src = (const uint4*)(g_w2t + (size_t)bn * C_DIM + bh * 32);
        uint4* dst = (uint4*)(Bsm + bn * B_STRIDE + bh * 32);
        dst[0] = src[0]; dst[1] = src[1]; dst[2] = src[2]; dst[3] = src[3];
    }
    __syncthreads();

    // ---- ldmatrix base addresses ----
    const int a_row = (lane & 7) + (lane & 8);         // 0..15
    const int a_col = (lane >> 4) * 8;                 // 0 or 8
    uint32_t a_base[2];
#pragma unroll
    for (int mt = 0; mt < 2; mt++)
        a_base[mt] = (uint32_t)__cvta_generic_to_shared(
            Asm + (warp_m * 32 + mt * 16 + a_row) * A_STRIDE + a_col);
    const int b_rowl = (lane >> 4);                    // nt sub-select
    const int b_coll = ((lane >> 3) & 1) * 8;          // k half
    uint32_t b_base[4];
#pragma unroll
    for (int p = 0; p < 4; p++) {
        int nrow = warp_n * 64 + (2 * p + b_rowl) * 8 + (lane & 7);
        b_base[p] = (uint32_t)__cvta_generic_to_shared(
            Bsm + nrow * B_STRIDE + b_coll);
    }

    float acc[2][8][4] = {};

    for (int c0 = 0; c0 < 4; c0++) {
        // prefetch next B chunk into the other buffer (overlaps with MMA)
        if (c0 < 3) {
            const uint4* src = (const uint4*)(g_w2t + (size_t)bn * C_DIM + (c0 + 1) * 64 + bh * 32);
            uint4* dst = (uint4*)(Bsm + ((c0 + 1) & 1) * B_BUF_ELEMS + bn * B_STRIDE + bh * 32);
            dst[0] = src[0]; dst[1] = src[1]; dst[2] = src[2]; dst[3] = src[3];
        }
        const uint32_t bufoff = (uint32_t)((c0 & 1) * B_BUF_ELEMS * 2);
#pragma unroll
        for (int kk = 0; kk < 64; kk += 16) {
            const int ka = c0 * 64 + kk;
            uint32_t a[2][4];
            LDSM_X4(a[0][0], a[0][1], a[0][2], a[0][3], a_base[0] + (uint32_t)(ka * 2));
            LDSM_X4(a[1][0], a[1][1], a[1][2], a[1][3], a_base[1] + (uint32_t)(ka * 2));
#pragma unroll
            for (int p = 0; p < 4; p++) {
                uint32_t b0, b1r, b2v, b3;
                LDSM_X4(b0, b1r, b2v, b3, b_base[p] + bufoff + (uint32_t)(kk * 2));
                MMA_BF16(acc[0][2 * p    ], a[0], b0, b1r);
                MMA_BF16(acc[1][2 * p    ], a[1], b0, b1r);
                MMA_BF16(acc[0][2 * p + 1], a[0], b2v, b3);
                MMA_BF16(acc[1][2 * p + 1], a[1], b2v, b3);
            }
        }
        __syncthreads();   // next buffer ready; current buffer reads done
    }

    // ---- register epilogue: softmax over K via 8-lane butterflies ----
    // Thread (warp_m, mt, gr, qg) holds point 2*warp_m+mt, neighbors gr and
    // gr+8, channels warp_n*64 + nt*8 + 2qg (+1). Reduction over 16 neighbors
    // = in-thread pair + butterfly over lane offsets {4, 8, 16} (qg fixed).
#pragma unroll
    for (int mt = 0; mt < 2; mt++) {
        int p_loc  = warp_m * 2 + mt;
        int p_glob = pt0 + p_loc;
        int j0 = idxs[p_loc * KNN + gr];
        int j1 = idxs[p_loc * KNN + gr + 8];
        const float* thp  = g_theta + (size_t)p_glob * C_DIM;
        const float* ph0p = g_phi + (size_t)j0 * C_DIM;
        const float* ph1p = g_phi + (size_t)j1 * C_DIM;
        const float* gf0p = g_gf  + (size_t)j0 * C_DIM;
        const float* gf1p = g_gf  + (size_t)j1 * C_DIM;
#pragma unroll
        for (int nt = 0; nt < 8; nt++) {
            int c = warp_n * 64 + nt * 8 + 2 * qg;
            float2 th = *(const float2*)(thp + c);
            float2 p0 = *(const float2*)(ph0p + c);
            float2 p1 = *(const float2*)(ph1p + c);
            float2 bb = *(const float2*)(b2 + c);
            float d00 = (acc[mt][nt][0] + bb.x) * (th.x - p0.x + 1.0f) * 0.0625f;
            float d01 = (acc[mt][nt][1] + bb.y) * (th.y - p0.y + 1.0f) * 0.0625f;
            float d10 = (acc[mt][nt][2] + bb.x) * (th.x - p1.x + 1.0f) * 0.0625f;
            float d11 = (acc[mt][nt][3] + bb.y) * (th.y - p1.y + 1.0f) * 0.0625f;
            float mx0 = fmaxf(d00, d10), mx1 = fmaxf(d01, d11);
#pragma unroll
            for (int o = 4; o < 32; o <<= 1) {
                mx0 = fmaxf(mx0, __shfl_xor_sync(0xffffffffu, mx0, o));
                mx1 = fmaxf(mx1, __shfl_xor_sync(0xffffffffu, mx1, o));
            }
            float e00 = __expf(d00 - mx0), e01 = __expf(d01 - mx1);
            float e10 = __expf(d10 - mx0), e11 = __expf(d11 - mx1);
            float s0 = e00 + e10, s1 = e01 + e11;
#pragma unroll
            for (int o = 4; o < 32; o <<= 1) {
                s0 += __shfl_xor_sync(0xffffffffu, s0, o);
                s1 += __shfl_xor_sync(0xffffffffu, s1, o);
            }
            float2 g0 = *(const float2*)(gf0p + c);
            float2 g1 = *(const float2*)(gf1p + c);
            float y0 = e00 * g0.x + e10 * g1.x;
            float y1 = e01 * g0.y + e11 * g1.y;
#pragma unroll
            for (int o = 4; o < 32; o <<= 1) {
                y0 += __shfl_xor_sync(0xffffffffu, y0, o);
                y1 += __shfl_xor_sync(0xffffffffu, y1, o);
            }
            if (gr == 0) {
                float2 outv = make_float2(y0 / s0, y1 / s1);
                *(float2*)(g_y + (size_t)p_glob * C_DIM + c) = outv;
            }
        }
    }
}

// ---------------- launch ----------------------------------------------------
static cudaStream_t s_gemm = nullptr, s_prep = nullptr;
static cudaEvent_t  ev_fork = nullptr, ev_gemm = nullptr, ev_prep = nullptr;

extern "C" void kernel_launch(void* const* d_in, const int* in_sizes, int n_in,
                              void* d_out, int out_size) {
    const float* coords  = (const float*)d_in[0];
    const float* feats   = (const float*)d_in[1];
    const float* theta_w = (const float*)d_in[2];
    const float* theta_b = (const float*)d_in[3];
    const float* phi_w   = (const float*)d_in[4];
    const float* phi_b   = (const float*)d_in[5];
    const float* g_w     = (const float*)d_in[6];
    const float* g_b     = (const float*)d_in[7];
    const float* pe1_w1  = (const float*)d_in[8];
    const float* pe1_b1  = (const float*)d_in[9];
    const float* pe1_w2  = (const float*)d_in[10];
    const float* pe1_b2  = (const float*)d_in[11];
    const float* W_w     = (const float*)d_in[12];
    const float* W_b     = (const float*)d_in[13];
    float* out = (float*)d_out;

    if (!s_gemm) {
        cudaStreamCreateWithFlags(&s_gemm, cudaStreamNonBlocking);
        cudaStreamCreateWithFlags(&s_prep, cudaStreamNonBlocking);
        cudaEventCreateWithFlags(&ev_fork, cudaEventDisableTiming);
        cudaEventCreateWithFlags(&ev_gemm, cudaEventDisableTiming);
        cudaEventCreateWithFlags(&ev_prep, cudaEventDisableTiming);
    }

    float *p_theta, *p_phi, *p_gf, *p_y;
    cudaGetSymbolAddress((void**)&p_theta, g_theta);
    cudaGetSymbolAddress((void**)&p_phi,   g_phi);
    cudaGetSymbolAddress((void**)&p_gf,    g_gf);
    cudaGetSymbolAddress((void**)&p_y,     g_y);

    cudaFuncSetAttribute(pe_attn3_kernel,
                         cudaFuncAttributeMaxDynamicSharedMemorySize, SMEM_TOTAL_PE);

    // fork point: side-stream work depends only on pre-chain state
    cudaEventRecord(ev_fork, 0);
    cudaStreamWaitEvent(s_gemm, ev_fork, 0);
    cudaStreamWaitEvent(s_prep, ev_fork, 0);

    // main stream: grid KNN chain (knn_grid is the 4th kernel launch -> profiled)
    cell_count_kernel<<<N_PTS / 256, 256>>>(coords);
    cell_scan_kernel<<<1, 512>>>();                       // also re-zeroes counts
    cell_scatter_kernel<<<N_PTS / 256, 256>>>(coords);
    knn_grid_kernel<<<N_PTS / KQPB, 256>>>(coords);

    // forked work (runs concurrently with the KNN chain)
    dim3 gt(C_DIM / 64, N_PTS / 128);   // (4, 64)
    gemm3_tf32_kernel<<<gt, 256, 0, s_gemm>>>(feats, theta_w, phi_w, g_w,
                                              theta_b, phi_b, g_b,
                                              p_theta, p_phi, p_gf);
    cudaEventRecord(ev_gemm, s_gemm);

    w2_prep_kernel<<<C_DIM * C_DIM / 256, 256, 0, s_prep>>>(pe1_w2);
    cudaEventRecord(ev_prep, s_prep);

    // join
    cudaStreamWaitEvent(0, ev_gemm, 0);
    cudaStreamWaitEvent(0, ev_prep, 0);

    pe_attn3_kernel<<<N_PTS * KNN / 128, 512, SMEM_TOTAL_PE>>>(pe1_w1, pe1_b1, pe1_b2);

    gemm_tf32_resid_kernel<<<gt, 256>>>(p_y, W_w, W_b, feats, out);
}